// round 2
// baseline (speedup 1.0000x reference)
#include <cuda_runtime.h>

#define H      20
#define NEX    13
#define EMBD   3
#define FIN    3
#define FOUT   5
#define HIN    8
#define HID    10
#define BLK    128
#define FROW   (H*FIN)   // 60 floats of f per row
#define ESTR   12        // padded row stride of E' table (floats)

// Precomputed tables (written by prep_kernel each launch; deterministic).
// g_E[(h*NEX+idx)*12 + j] = emb[idx]@W1[h][0:3,j] + b1[h][j] + bf@W1[h][3:8,j]
// g_W[h*64 + c*16 + j]    = (Wf @ W1[h][3:8])[c][j]   (c=0..2, j=0..9)
// g_W[h*64 + 48 + j]      = W2[h][j]
// g_W[h*64 + 58]          = Wo[h]
__device__ __align__(16) float g_E[H * NEX * ESTR];
__device__ __align__(16) float g_W[H * 64];

__global__ void prep_kernel(const float* __restrict__ emb,
                            const float* __restrict__ Wf,
                            const float* __restrict__ bf,
                            const float* __restrict__ W1,
                            const float* __restrict__ b1,
                            const float* __restrict__ W2,
                            const float* __restrict__ Wo)
{
    const int tid = threadIdx.x;
    // E' table: 20*13*10 entries
    for (int i = tid; i < H * NEX * HID; i += blockDim.x) {
        const int h   = i / (NEX * HID);
        const int r   = i % (NEX * HID);
        const int idx = r / HID;
        const int j   = r % HID;
        float v = b1[h * HID + j];
        for (int k = 0; k < FOUT; k++)
            v += bf[k] * W1[(h * HIN + 3 + k) * HID + j];
        for (int d = 0; d < EMBD; d++)
            v += emb[idx * EMBD + d] * W1[(h * HIN + d) * HID + j];
        g_E[(h * NEX + idx) * ESTR + j] = v;
    }
    // Wc = Wf @ W1[:,3:8,:]
    for (int i = tid; i < H * FIN * HID; i += blockDim.x) {
        const int h = i / (FIN * HID);
        const int r = i % (FIN * HID);
        const int c = r / HID;
        const int j = r % HID;
        float v = 0.0f;
        for (int k = 0; k < FOUT; k++)
            v += Wf[c * FOUT + k] * W1[(h * HIN + 3 + k) * HID + j];
        g_W[h * 64 + c * 16 + j] = v;
    }
    // W2 and Wo
    for (int i = tid; i < H * HID; i += blockDim.x) {
        const int h = i / HID, j = i % HID;
        g_W[h * 64 + 48 + j] = W2[i];
    }
    for (int i = tid; i < H; i += blockDim.x) {
        g_W[i * 64 + 58] = Wo[i];
        g_W[i * 64 + 59] = 0.0f;   // pad read by the w2-tail float4, must be finite
    }
}

__global__ __launch_bounds__(BLK)
void airfit_main(const int*   __restrict__ e,
                 const float* __restrict__ f,
                 const float* __restrict__ bo,
                 float*       __restrict__ out,
                 int n)
{
    __shared__ float s_f[BLK][61];                 // 61 odd -> conflict-free per-lane reads
    __shared__ __align__(16) float s_E[H * NEX * ESTR];   // 12480 B
    __shared__ unsigned int s_e[BLK * H / 4];      // indices packed as bytes, 2560 B

    const int tid = threadIdx.x;
    const long long b0 = (long long)blockIdx.x * BLK;
    const long long b  = b0 + tid;

    int rows = n - (int)b0;
    if (rows > BLK) rows = BLK;
    if (rows < 0)   rows = 0;

    // ---- stage E' table (uniform, float4 copies) ----
    {
        const float4* src = reinterpret_cast<const float4*>(g_E);
        float4*       dst = reinterpret_cast<float4*>(s_E);
        for (int i = tid; i < H * NEX * ESTR / 4; i += BLK) dst[i] = src[i];
    }

    // ---- stage e coalesced: int4 loads, pack 4 indices into one word ----
    {
        const int4* eg = reinterpret_cast<const int4*>(e + b0 * H);
        const int nv = rows * H / 4;               // H=20, rows*20 % 4 == 0
        for (int v = tid; v < nv; v += BLK) {
            int4 val = eg[v];
            s_e[v] = (unsigned)(val.x & 0xFF)
                   | ((unsigned)(val.y & 0xFF) << 8)
                   | ((unsigned)(val.z & 0xFF) << 16)
                   | ((unsigned)(val.w & 0xFF) << 24);
        }
    }

    // ---- stage f coalesced float4 -> padded rows ----
    {
        const float4* fg = reinterpret_cast<const float4*>(f + b0 * FROW);
        const int nf4 = rows * (FROW / 4);
        for (int v = tid; v < nf4; v += BLK) {
            float4 val = fg[v];
            const int fl  = v * 4;
            const int row = fl / FROW;
            const int col = fl % FROW;
            s_f[row][col + 0] = val.x;
            s_f[row][col + 1] = val.y;
            s_f[row][col + 2] = val.z;
            s_f[row][col + 3] = val.w;
        }
    }
    __syncthreads();

    if (b >= n) return;

    const unsigned char* my_e = reinterpret_cast<const unsigned char*>(s_e) + tid * H;
    float acc = __ldg(bo);

#pragma unroll 4
    for (int h = 0; h < H; h++) {
        const int idx = (int)my_e[h];

        // accumulators initialized from the bias-folded embedding table
        const float* Ep = &s_E[(h * NEX + idx) * ESTR];
        float4 t0 = *reinterpret_cast<const float4*>(Ep);
        float4 t1 = *reinterpret_cast<const float4*>(Ep + 4);
        float2 t2 = *reinterpret_cast<const float2*>(Ep + 8);

        const float f0 = s_f[tid][h * 3 + 0];
        const float f1 = s_f[tid][h * 3 + 1];
        const float f2 = s_f[tid][h * 3 + 2];

        const float* W = g_W + h * 64;
        // c = 0..2: t += fc * Wc[c]   (warp-uniform LDGs, L1 broadcast)
        {
            const float4 w0 = __ldg(reinterpret_cast<const float4*>(W + 0));
            const float4 w1 = __ldg(reinterpret_cast<const float4*>(W + 4));
            const float2 w2 = __ldg(reinterpret_cast<const float2*>(W + 8));
            t0.x = fmaf(f0, w0.x, t0.x); t0.y = fmaf(f0, w0.y, t0.y);
            t0.z = fmaf(f0, w0.z, t0.z); t0.w = fmaf(f0, w0.w, t0.w);
            t1.x = fmaf(f0, w1.x, t1.x); t1.y = fmaf(f0, w1.y, t1.y);
            t1.z = fmaf(f0, w1.z, t1.z); t1.w = fmaf(f0, w1.w, t1.w);
            t2.x = fmaf(f0, w2.x, t2.x); t2.y = fmaf(f0, w2.y, t2.y);
        }
        {
            const float4 w0 = __ldg(reinterpret_cast<const float4*>(W + 16));
            const float4 w1 = __ldg(reinterpret_cast<const float4*>(W + 20));
            const float2 w2 = __ldg(reinterpret_cast<const float2*>(W + 24));
            t0.x = fmaf(f1, w0.x, t0.x); t0.y = fmaf(f1, w0.y, t0.y);
            t0.z = fmaf(f1, w0.z, t0.z); t0.w = fmaf(f1, w0.w, t0.w);
            t1.x = fmaf(f1, w1.x, t1.x); t1.y = fmaf(f1, w1.y, t1.y);
            t1.z = fmaf(f1, w1.z, t1.z); t1.w = fmaf(f1, w1.w, t1.w);
            t2.x = fmaf(f1, w2.x, t2.x); t2.y = fmaf(f1, w2.y, t2.y);
        }
        {
            const float4 w0 = __ldg(reinterpret_cast<const float4*>(W + 32));
            const float4 w1 = __ldg(reinterpret_cast<const float4*>(W + 36));
            const float2 w2 = __ldg(reinterpret_cast<const float2*>(W + 40));
            t0.x = fmaf(f2, w0.x, t0.x); t0.y = fmaf(f2, w0.y, t0.y);
            t0.z = fmaf(f2, w0.z, t0.z); t0.w = fmaf(f2, w0.w, t0.w);
            t1.x = fmaf(f2, w1.x, t1.x); t1.y = fmaf(f2, w1.y, t1.y);
            t1.z = fmaf(f2, w1.z, t1.z); t1.w = fmaf(f2, w1.w, t1.w);
            t2.x = fmaf(f2, w2.x, t2.x); t2.y = fmaf(f2, w2.y, t2.y);
        }

        // leaky_relu(t) = max(t, 0.01*t), then dot with W2; Wo rides in the tail
        const float4 v0 = __ldg(reinterpret_cast<const float4*>(W + 48));
        const float4 v1 = __ldg(reinterpret_cast<const float4*>(W + 52));
        const float4 v2 = __ldg(reinterpret_cast<const float4*>(W + 56)); // W2[8],W2[9],Wo,pad
        #define LK(v) fmaxf((v), 0.01f * (v))
        float z = __ldg(W + 62 - 62);  // dummy-free init below
        z  = LK(t0.x) * v0.x;
        z  = fmaf(LK(t0.y), v0.y, z);
        z  = fmaf(LK(t0.z), v0.z, z);
        z  = fmaf(LK(t0.w), v0.w, z);
        z  = fmaf(LK(t1.x), v1.x, z);
        z  = fmaf(LK(t1.y), v1.y, z);
        z  = fmaf(LK(t1.z), v1.z, z);
        z  = fmaf(LK(t1.w), v1.w, z);
        z  = fmaf(LK(t2.x), v2.x, z);
        z  = fmaf(LK(t2.y), v2.y, z);
        #undef LK
        // b2 was NOT folded into E' (it is outside the leaky input? no -- b2 is
        // added AFTER leaky in ref: softplus(h1@W2 + b2)). Load b2 via tail pad.
        // v2.z = Wo[h]; b2 handled below via g_W? -> b2 folded here:
        z += __ldg(W + 63);

        const float sp = fmaxf(z, 0.0f) + __logf(1.0f + __expf(-fabsf(z)));
        acc = fmaf(sp, v2.z, acc);
    }

    out[b] = acc;
}

// second prep pass writes b2 into g_W[h*64+63]
__global__ void prep_b2(const float* __restrict__ b2)
{
    const int tid = threadIdx.x;
    if (tid < H) g_W[tid * 64 + 63] = b2[tid];
}

extern "C" void kernel_launch(void* const* d_in, const int* in_sizes, int n_in,
                              void* d_out, int out_size)
{
    const int*   e   = (const int*)  d_in[0];
    const float* f   = (const float*)d_in[1];
    const float* emb = (const float*)d_in[2];
    const float* Wf  = (const float*)d_in[3];
    const float* bf  = (const float*)d_in[4];
    const float* W1  = (const float*)d_in[5];
    const float* b1  = (const float*)d_in[6];
    const float* W2  = (const float*)d_in[7];
    const float* b2  = (const float*)d_in[8];
    const float* Wo  = (const float*)d_in[9];
    const float* bo  = (const float*)d_in[10];
    float* out = (float*)d_out;

    const int n = in_sizes[0] / H;
    prep_kernel<<<1, 256>>>(emb, Wf, bf, W1, b1, W2, Wo);
    prep_b2<<<1, 32>>>(b2);
    const int grid = (n + BLK - 1) / BLK;
    airfit_main<<<grid, BLK>>>(e, f, bo, out, n);
}

// round 3
// speedup vs baseline: 1.5644x; 1.5644x over previous
#include <cuda_runtime.h>

#define H      20
#define NEX    13
#define EMBD   3
#define FIN    3
#define FOUT   5
#define HIN    8
#define HID    10
#define BLK    128
#define FROW   (H*FIN)    // 60 floats of f per row
#define WSTR   48         // per-head packed weight stride (floats)
#define ESTR   10         // E' row stride (floats), LDS.64-friendly

// Packed tables built by prep_kernel each launch (deterministic):
// g_E[(h*NEX+idx)*10 + j] = emb[idx]@W1[h][0:3,j] + b1[h][j] + bf@W1[h][3:8,j]
// g_W[h*48 + c*12 + j]    = (Wf @ W1[h][3:8])[c][j]  (c=0..2, j=0..9; pads 0)
// g_W[h*48 + 36 + j]      = W2[h][j]   (j=0..9)
// g_W[h*48 + 46]          = b2[h]
// g_W[h*48 + 47]          = Wo[h]
__device__ __align__(16) float g_E[H * NEX * ESTR];   // 2600 floats
__device__ __align__(16) float g_W[H * WSTR];         // 960 floats

__global__ void prep_kernel(const float* __restrict__ emb,
                            const float* __restrict__ Wf,
                            const float* __restrict__ bf,
                            const float* __restrict__ W1,
                            const float* __restrict__ b1,
                            const float* __restrict__ W2,
                            const float* __restrict__ b2,
                            const float* __restrict__ Wo)
{
    const int g = blockIdx.x * blockDim.x + threadIdx.x;
    const int NE = H * NEX * ESTR;          // 2600
    if (g < NE) {
        const int h   = g / (NEX * ESTR);
        const int r   = g % (NEX * ESTR);
        const int idx = r / ESTR;
        const int j   = r % ESTR;
        float v = b1[h * HID + j];
#pragma unroll
        for (int k = 0; k < FOUT; k++)
            v = fmaf(bf[k], W1[(h * HIN + 3 + k) * HID + j], v);
#pragma unroll
        for (int d = 0; d < EMBD; d++)
            v = fmaf(emb[idx * EMBD + d], W1[(h * HIN + d) * HID + j], v);
        g_E[g] = v;
    } else if (g < NE + H * WSTR) {
        const int w = g - NE;
        const int h = w / WSTR;
        const int j = w % WSTR;
        float v = 0.0f;
        if (j < 36) {
            const int c  = j / 12;
            const int jj = j % 12;
            if (jj < HID) {
#pragma unroll
                for (int k = 0; k < FOUT; k++)
                    v = fmaf(Wf[c * FOUT + k], W1[(h * HIN + 3 + k) * HID + jj], v);
            }
        } else if (j < 46) {
            v = W2[h * HID + (j - 36)];
        } else if (j == 46) {
            v = b2[h];
        } else {
            v = Wo[h];
        }
        g_W[w] = v;
    }
}

__global__ __launch_bounds__(BLK)
void airfit_main(const int*   __restrict__ e,
                 const float* __restrict__ f,
                 const float* __restrict__ bo,
                 float*       __restrict__ out,
                 int n)
{
    // 48032 bytes total static shared (< 48 KB)
    __shared__ __align__(16) float        s_E[H * NEX * ESTR];  // 10400 B
    __shared__ __align__(16) float        s_W[H * WSTR];        //  3840 B
    __shared__              float         s_f[BLK * 61];        // 31232 B (61: gcd(61,32)=1)
    __shared__              unsigned int  s_e[BLK * H / 4];     //  2560 B

    const int tid = threadIdx.x;
    const long long b0 = (long long)blockIdx.x * BLK;
    const long long b  = b0 + tid;

    int rows = n - (int)b0;
    if (rows > BLK) rows = BLK;
    if (rows < 0)   rows = 0;

    // ---- stage E' + W tables (uniform float4 copies; 3560 floats = 890 f4) ----
    {
        const float4* srcE = reinterpret_cast<const float4*>(g_E);
        float4*       dstE = reinterpret_cast<float4*>(s_E);
#pragma unroll
        for (int i = tid; i < H * NEX * ESTR / 4; i += BLK) dstE[i] = srcE[i];
        const float4* srcW = reinterpret_cast<const float4*>(g_W);
        float4*       dstW = reinterpret_cast<float4*>(s_W);
#pragma unroll
        for (int i = tid; i < H * WSTR / 4; i += BLK) dstW[i] = srcW[i];
    }

    // ---- stage e coalesced: int4 loads, 4 indices packed per word ----
    {
        const int4* eg = reinterpret_cast<const int4*>(e + b0 * H);
        const int nv = rows * (H / 4) + (rows * (H % 4)) / 4;   // rows*5
        for (int v = tid; v < nv; v += BLK) {
            int4 val = eg[v];
            s_e[v] = (unsigned)(val.x & 0xFF)
                   | ((unsigned)(val.y & 0xFF) << 8)
                   | ((unsigned)(val.z & 0xFF) << 16)
                   | ((unsigned)(val.w & 0xFF) << 24);
        }
    }

    // ---- stage f coalesced float4 -> padded rows (stride 61) ----
    {
        const float4* fg = reinterpret_cast<const float4*>(f + b0 * FROW);
        const int nf4 = rows * (FROW / 4);
        for (int v = tid; v < nf4; v += BLK) {
            float4 val = fg[v];
            const int fl  = v * 4;
            const int row = fl / FROW;
            const int col = fl % FROW;
            float* dst = &s_f[row * 61 + col];
            dst[0] = val.x; dst[1] = val.y; dst[2] = val.z; dst[3] = val.w;
        }
    }
    __syncthreads();

    if (b >= n) return;

    const unsigned char* my_e = reinterpret_cast<const unsigned char*>(s_e) + tid * H;
    const float* my_f = &s_f[tid * 61];
    float acc = __ldg(bo);

#pragma unroll 2
    for (int h = 0; h < H; h++) {
        const int idx = (int)my_e[h];

        // accumulators init from bias-folded embedding table (5x LDS.64)
        const float* Ep = &s_E[(h * NEX + idx) * ESTR];
        float2 t0 = *reinterpret_cast<const float2*>(Ep + 0);
        float2 t1 = *reinterpret_cast<const float2*>(Ep + 2);
        float2 t2 = *reinterpret_cast<const float2*>(Ep + 4);
        float2 t3 = *reinterpret_cast<const float2*>(Ep + 6);
        float2 t4 = *reinterpret_cast<const float2*>(Ep + 8);

        const float f0 = my_f[h * 3 + 0];
        const float f1 = my_f[h * 3 + 1];
        const float f2 = my_f[h * 3 + 2];

        const float* W = &s_W[h * WSTR];
#pragma unroll
        for (int c = 0; c < 3; c++) {
            const float fc = (c == 0) ? f0 : (c == 1) ? f1 : f2;
            const float4 w0 = *reinterpret_cast<const float4*>(W + c * 12 + 0);
            const float4 w1 = *reinterpret_cast<const float4*>(W + c * 12 + 4);
            const float2 w2 = *reinterpret_cast<const float2*>(W + c * 12 + 8);
            t0.x = fmaf(fc, w0.x, t0.x); t0.y = fmaf(fc, w0.y, t0.y);
            t1.x = fmaf(fc, w0.z, t1.x); t1.y = fmaf(fc, w0.w, t1.y);
            t2.x = fmaf(fc, w1.x, t2.x); t2.y = fmaf(fc, w1.y, t2.y);
            t3.x = fmaf(fc, w1.z, t3.x); t3.y = fmaf(fc, w1.w, t3.y);
            t4.x = fmaf(fc, w2.x, t4.x); t4.y = fmaf(fc, w2.y, t4.y);
        }

        // leaky_relu then dot with W2; v2 = (W2[8], W2[9], b2, Wo)
        const float4 v0 = *reinterpret_cast<const float4*>(W + 36);
        const float4 v1 = *reinterpret_cast<const float4*>(W + 40);
        const float4 v2 = *reinterpret_cast<const float4*>(W + 44);
        #define LK(v) fmaxf((v), 0.01f * (v))
        float z = v2.z;                       // b2
        z = fmaf(LK(t0.x), v0.x, z);
        z = fmaf(LK(t0.y), v0.y, z);
        z = fmaf(LK(t1.x), v0.z, z);
        z = fmaf(LK(t1.y), v0.w, z);
        z = fmaf(LK(t2.x), v1.x, z);
        z = fmaf(LK(t2.y), v1.y, z);
        z = fmaf(LK(t3.x), v1.z, z);
        z = fmaf(LK(t3.y), v1.w, z);
        z = fmaf(LK(t4.x), v2.x, z);
        z = fmaf(LK(t4.y), v2.y, z);
        #undef LK

        // softplus = max(z,0) + log1p(exp(-|z|))
        const float sp = fmaxf(z, 0.0f) + __logf(1.0f + __expf(-fabsf(z)));
        acc = fmaf(sp, v2.w, acc);            // Wo
    }

    out[b] = acc;
}

extern "C" void kernel_launch(void* const* d_in, const int* in_sizes, int n_in,
                              void* d_out, int out_size)
{
    const int*   e   = (const int*)  d_in[0];
    const float* f   = (const float*)d_in[1];
    const float* emb = (const float*)d_in[2];
    const float* Wf  = (const float*)d_in[3];
    const float* bf  = (const float*)d_in[4];
    const float* W1  = (const float*)d_in[5];
    const float* b1  = (const float*)d_in[6];
    const float* W2  = (const float*)d_in[7];
    const float* b2  = (const float*)d_in[8];
    const float* Wo  = (const float*)d_in[9];
    const float* bo  = (const float*)d_in[10];
    float* out = (float*)d_out;

    const int n = in_sizes[0] / H;

    // 2600 + 960 = 3560 elements, one per thread
    prep_kernel<<<(3560 + 255) / 256, 256>>>(emb, Wf, bf, W1, b1, W2, b2, Wo);

    const int grid = (n + BLK - 1) / BLK;
    airfit_main<<<grid, BLK>>>(e, f, bo, out, n);
}